// round 3
// baseline (speedup 1.0000x reference)
#include <cuda_runtime.h>
#include <math.h>
#include <stdint.h>

#define BB 256
#define LL 200
#define DD 512

// ---------------- scratch ----------------
__device__ float g_xproj[(size_t)BB * LL * 3 * DD];   // [B,L,3D] GRU input proj (+bih)
__device__ float g_sseq [(size_t)LL * BB * DD];       // [L,B,D] GRU outputs
__device__ float g_rx   [(size_t)LL * BB * DD];       // AUGRU x-projections (+bias), [L,B,D]
__device__ float g_ux   [(size_t)LL * BB * DD];
__device__ float g_nx   [(size_t)LL * BB * DD];
__device__ float g_u    [BB * DD];
__device__ float g_logits[LL * BB];
__device__ float g_att   [LL * BB];
__device__ float g_r     [BB * DD];
__device__ float g_ue    [BB * DD];
__device__ float g_h     [2 * BB * DD];
__device__ float g_hp    [BB * 3 * DD];               // GRU h-projection scratch
__device__ float g_zero  [BB * DD];

__device__ __forceinline__ float sigf(float x) { return 1.0f / (1.0f + __expf(-x)); }

__device__ __forceinline__ uint32_t tf32r(float x) {
    uint32_t r;
    asm("cvt.rna.tf32.f32 %0, %1;" : "=r"(r) : "f"(x));
    return r;
}

__device__ __forceinline__ void mma8(float* d, const uint32_t* a, const uint32_t* b) {
    asm volatile(
        "mma.sync.aligned.m16n8k8.row.col.f32.tf32.tf32.f32 "
        "{%0,%1,%2,%3}, {%4,%5,%6,%7}, {%8,%9}, {%0,%1,%2,%3};"
        : "+f"(d[0]), "+f"(d[1]), "+f"(d[2]), "+f"(d[3])
        : "r"(a[0]), "r"(a[1]), "r"(a[2]), "r"(a[3]), "r"(b[0]), "r"(b[1]));
}

// ============ 64x64xK=512 tf32 core (3xTF32), 128 threads, double-buffered ============
// C[m,n] = sum_k A[m,k] * W[n,k]. Arow = A + mbase*lda. Wrow = W + nbase*ldw + woff.
// MULR: A elementwise-multiplied by R (same layout) at load time.
template<bool MULR>
__device__ __forceinline__ void mm_core64(
    const float* __restrict__ Arow, const float* __restrict__ Rrow, int lda,
    const float* __restrict__ Wrow, int ldw,
    float acc[2][4][4])
{
    __shared__ uint32_t Ah[2][16][72], Al[2][16][72];
    __shared__ uint32_t Wh[2][16][72], Wl[2][16][72];

    const int tid  = threadIdx.x;
    const int lr   = tid >> 1;           // 0..63 (row of tile)
    const int lk   = (tid & 1) << 3;     // 0 or 8 (k offset)
    const int lane = tid & 31;
    const int g    = lane >> 2;          // groupID
    const int t    = lane & 3;           // threadID in group
    const int w    = tid >> 5;
    const int mb   = (w >> 1) * 32;      // warp m base
    const int nb   = (w & 1) * 32;       // warp n base

    const float* ap = Arow + (size_t)lr * lda + lk;
    const float* rp = MULR ? (Rrow + (size_t)lr * lda + lk) : nullptr;
    const float* wp = Wrow + (size_t)lr * ldw + lk;

    float va[8], vw[8];

    auto GLOAD = [&](int k0) {
        float4 a0 = *(const float4*)(ap + k0);
        float4 a1 = *(const float4*)(ap + k0 + 4);
        float4 w0 = *(const float4*)(wp + k0);
        float4 w1 = *(const float4*)(wp + k0 + 4);
        if (MULR) {
            float4 r0 = *(const float4*)(rp + k0);
            float4 r1 = *(const float4*)(rp + k0 + 4);
            a0.x *= r0.x; a0.y *= r0.y; a0.z *= r0.z; a0.w *= r0.w;
            a1.x *= r1.x; a1.y *= r1.y; a1.z *= r1.z; a1.w *= r1.w;
        }
        va[0] = a0.x; va[1] = a0.y; va[2] = a0.z; va[3] = a0.w;
        va[4] = a1.x; va[5] = a1.y; va[6] = a1.z; va[7] = a1.w;
        vw[0] = w0.x; vw[1] = w0.y; vw[2] = w0.z; vw[3] = w0.w;
        vw[4] = w1.x; vw[5] = w1.y; vw[6] = w1.z; vw[7] = w1.w;
    };

    auto STS = [&](int s) {
        #pragma unroll
        for (int i = 0; i < 8; i++) {
            uint32_t ha = tf32r(va[i]);
            Ah[s][lk + i][lr] = ha;
            Al[s][lk + i][lr] = tf32r(va[i] - __uint_as_float(ha));
            uint32_t hw = tf32r(vw[i]);
            Wh[s][lk + i][lr] = hw;
            Wl[s][lk + i][lr] = tf32r(vw[i] - __uint_as_float(hw));
        }
    };

    auto COMP = [&](int s) {
        #pragma unroll
        for (int ks = 0; ks < 2; ks++) {
            const int kk = ks << 3;
            uint32_t ah[2][4], al[2][4], bh[4][2], bl[4][2];
            #pragma unroll
            for (int i = 0; i < 2; i++) {
                int m0 = mb + i * 16 + g;
                ah[i][0] = Ah[s][kk + t][m0];     ah[i][1] = Ah[s][kk + t][m0 + 8];
                ah[i][2] = Ah[s][kk + t + 4][m0]; ah[i][3] = Ah[s][kk + t + 4][m0 + 8];
                al[i][0] = Al[s][kk + t][m0];     al[i][1] = Al[s][kk + t][m0 + 8];
                al[i][2] = Al[s][kk + t + 4][m0]; al[i][3] = Al[s][kk + t + 4][m0 + 8];
            }
            #pragma unroll
            for (int j = 0; j < 4; j++) {
                int n0 = nb + j * 8 + g;
                bh[j][0] = Wh[s][kk + t][n0]; bh[j][1] = Wh[s][kk + t + 4][n0];
                bl[j][0] = Wl[s][kk + t][n0]; bl[j][1] = Wl[s][kk + t + 4][n0];
            }
            #pragma unroll
            for (int i = 0; i < 2; i++)
                #pragma unroll
                for (int j = 0; j < 4; j++) {
                    mma8(acc[i][j], ah[i], bh[j]);   // hi*hi
                    mma8(acc[i][j], al[i], bh[j]);   // lo*hi
                    mma8(acc[i][j], ah[i], bl[j]);   // hi*lo
                }
        }
    };

    GLOAD(0);
    STS(0);
    __syncthreads();
    #pragma unroll 1
    for (int it = 1; it < DD / 16; it++) {
        GLOAD(it * 16);
        COMP((it - 1) & 1);
        STS(it & 1);
        __syncthreads();
    }
    COMP((DD / 16 - 1) & 1);
}

#define EPI_SETUP() \
    const int lane = threadIdx.x & 31; \
    const int g = lane >> 2, t = lane & 3; \
    const int w = threadIdx.x >> 5; \
    const int wm = w >> 1, wn = w & 1;

// ---------------- generic NT GEMM (+bias) ----------------
__global__ __launch_bounds__(128) void mm_big(
    const float* __restrict__ A, int lda,
    const float* __restrict__ W, int ldw, int woff,
    const float* __restrict__ bias,
    float* __restrict__ C, int ldc)
{
    float acc[2][4][4];
    #pragma unroll
    for (int i = 0; i < 2; i++)
        #pragma unroll
        for (int j = 0; j < 4; j++)
            #pragma unroll
            for (int e = 0; e < 4; e++) acc[i][j][e] = 0.f;

    mm_core64<false>(A + (size_t)blockIdx.x * 64 * lda, nullptr, lda,
                     W + (size_t)blockIdx.y * 64 * ldw + woff, ldw, acc);

    EPI_SETUP();
    const int r0 = blockIdx.x * 64 + wm * 32 + g;
    const int c0 = blockIdx.y * 64 + wn * 32 + 2 * t;
    #pragma unroll
    for (int i = 0; i < 2; i++)
        #pragma unroll
        for (int j = 0; j < 4; j++) {
            int rr = r0 + i * 16;
            int cc = c0 + j * 8;
            float b0 = bias ? bias[cc] : 0.f;
            float b1 = bias ? bias[cc + 1] : 0.f;
            *(float2*)(C + (size_t)rr * ldc + cc) =
                make_float2(acc[i][j][0] + b0, acc[i][j][1] + b1);
            *(float2*)(C + (size_t)(rr + 8) * ldc + cc) =
                make_float2(acc[i][j][2] + b0, acc[i][j][3] + b1);
        }
}

// ---------------- GRU gating (elementwise) ----------------
__global__ void gru_gate(const float* __restrict__ hp,     // [B,3D] (+bhh)
                         const float* __restrict__ xproj,  // [B,L,3D] (+bih)
                         int l,
                         const float* __restrict__ hprev,  // [B,D]
                         float* __restrict__ hout)         // [B,D]
{
    int e = blockIdx.x * 256 + threadIdx.x;     // 0 .. B*D-1
    int b = e >> 9, n = e & (DD - 1);
    const float* xr = xproj + ((size_t)b * LL + l) * 3 * DD;
    const float* hr = hp + (size_t)b * 3 * DD;
    float r  = sigf(xr[n] + hr[n]);
    float z  = sigf(xr[DD + n] + hr[DD + n]);
    float nn = tanhf(xr[2 * DD + n] + r * hr[2 * DD + n]);
    float h0 = hprev[e];
    hout[e] = (1.f - z) * nn + z * h0;
}

// ---------------- AUGRU phase A: fused r / u_eff ----------------
__global__ __launch_bounds__(128) void mm_aua(
    const float* __restrict__ h,
    const float* __restrict__ Wr, const float* __restrict__ Wu,
    const float* __restrict__ rxl, const float* __restrict__ uxl,
    const float* __restrict__ attl,
    float* __restrict__ rbuf, float* __restrict__ uebuf)
{
    const int gate = blockIdx.z;
    const float* W = gate ? Wu : Wr;
    const float* X = gate ? uxl : rxl;

    float acc[2][4][4];
    #pragma unroll
    for (int i = 0; i < 2; i++)
        #pragma unroll
        for (int j = 0; j < 4; j++)
            #pragma unroll
            for (int e = 0; e < 4; e++) acc[i][j][e] = 0.f;

    mm_core64<false>(h + (size_t)blockIdx.x * 64 * DD, nullptr, DD,
                     W + (size_t)blockIdx.y * 64 * (2 * DD), 2 * DD, acc);

    EPI_SETUP();
    const int r0 = blockIdx.x * 64 + wm * 32 + g;
    const int c0 = blockIdx.y * 64 + wn * 32 + 2 * t;
    #pragma unroll
    for (int i = 0; i < 2; i++)
        #pragma unroll
        for (int j = 0; j < 4; j++) {
            int cc = c0 + j * 8;
            #pragma unroll
            for (int half = 0; half < 2; half++) {
                int rr = r0 + i * 16 + half * 8;
                size_t idx = (size_t)rr * DD + cc;
                float v0 = acc[i][j][half * 2 + 0] + X[idx];
                float v1 = acc[i][j][half * 2 + 1] + X[idx + 1];
                if (gate == 0) {
                    *(float2*)(rbuf + idx) = make_float2(sigf(v0), sigf(v1));
                } else {
                    float a = attl[rr];
                    *(float2*)(uebuf + idx) = make_float2(a * sigf(v0), a * sigf(v1));
                }
            }
        }
}

// ---------------- AUGRU phase B: fused hhat + output ----------------
__global__ __launch_bounds__(128) void mm_aub(
    const float* __restrict__ h,
    const float* __restrict__ rbuf,
    const float* __restrict__ Whh_,   // hhat_w [D,2D], h-half (woff=0)
    const float* __restrict__ nxl,
    const float* __restrict__ uebuf,
    float* __restrict__ hout)
{
    float acc[2][4][4];
    #pragma unroll
    for (int i = 0; i < 2; i++)
        #pragma unroll
        for (int j = 0; j < 4; j++)
            #pragma unroll
            for (int e = 0; e < 4; e++) acc[i][j][e] = 0.f;

    mm_core64<true>(h + (size_t)blockIdx.x * 64 * DD,
                    rbuf + (size_t)blockIdx.x * 64 * DD, DD,
                    Whh_ + (size_t)blockIdx.y * 64 * (2 * DD), 2 * DD, acc);

    EPI_SETUP();
    const int r0 = blockIdx.x * 64 + wm * 32 + g;
    const int c0 = blockIdx.y * 64 + wn * 32 + 2 * t;
    #pragma unroll
    for (int i = 0; i < 2; i++)
        #pragma unroll
        for (int j = 0; j < 4; j++) {
            int cc = c0 + j * 8;
            #pragma unroll
            for (int half = 0; half < 2; half++) {
                int rr = r0 + i * 16 + half * 8;
                size_t idx = (size_t)rr * DD + cc;
                float hh0 = tanhf(acc[i][j][half * 2 + 0] + nxl[idx]);
                float hh1 = tanhf(acc[i][j][half * 2 + 1] + nxl[idx + 1]);
                float ue0 = uebuf[idx], ue1 = uebuf[idx + 1];
                float h0 = h[idx], h1 = h[idx + 1];
                *(float2*)(hout + idx) =
                    make_float2(h0 + ue0 * (hh0 - h0), h1 + ue1 * (hh1 - h1));
            }
        }
}

// ---------------- attention ----------------
__global__ void attn_logits(const float* __restrict__ s,   // s_seq [L,B,D]
                            const float* __restrict__ u,   // [B,D]
                            float* __restrict__ logits)    // [L,B]
{
    int gw = (blockIdx.x * blockDim.x + threadIdx.x) >> 5;
    int lane = threadIdx.x & 31;
    int b = gw & (BB - 1);
    const float4* sr = (const float4*)(s + (size_t)gw * DD);
    const float4* ur = (const float4*)(u + (size_t)b * DD);
    float acc = 0.f;
    #pragma unroll
    for (int k = lane; k < DD / 4; k += 32) {
        float4 a = sr[k], c = ur[k];
        acc += a.x * c.x + a.y * c.y + a.z * c.z + a.w * c.w;
    }
    #pragma unroll
    for (int o = 16; o > 0; o >>= 1) acc += __shfl_xor_sync(0xffffffffu, acc, o);
    if (lane == 0) logits[gw] = acc;
}

__global__ void attn_softmax(const float* __restrict__ logits, float* __restrict__ att)
{
    int b = blockIdx.x, t = threadIdx.x;
    __shared__ float red[256];
    float v = (t < LL) ? logits[t * BB + b] : -1e30f;
    red[t] = v;
    __syncthreads();
    for (int s = 128; s > 0; s >>= 1) {
        if (t < s) red[t] = fmaxf(red[t], red[t + s]);
        __syncthreads();
    }
    float mx = red[0];
    __syncthreads();
    float e = (t < LL) ? expf(v - mx) : 0.f;
    red[t] = e;
    __syncthreads();
    for (int s = 128; s > 0; s >>= 1) {
        if (t < s) red[t] += red[t + s];
        __syncthreads();
    }
    float inv = 1.f / red[0];
    if (t < LL) att[t * BB + b] = e * inv;
}

__global__ void zero_kernel(float* __restrict__ p, int n)
{
    int i = blockIdx.x * blockDim.x + threadIdx.x;
    if (i < n) p[i] = 0.f;
}

// ---------------- host ----------------
extern "C" void kernel_launch(void* const* d_in, const int* in_sizes, int n_in,
                              void* d_out, int out_size)
{
    const float* session  = (const float*)d_in[0];
    const float* target   = (const float*)d_in[1];
    const float* w        = (const float*)d_in[2];
    const float* wih      = (const float*)d_in[3];
    const float* whh      = (const float*)d_in[4];
    const float* bih      = (const float*)d_in[5];
    const float* bhh      = (const float*)d_in[6];
    const float* reset_w  = (const float*)d_in[7];
    const float* reset_b  = (const float*)d_in[8];
    const float* update_w = (const float*)d_in[9];
    const float* update_b = (const float*)d_in[10];
    const float* hhat_w   = (const float*)d_in[11];
    const float* hhat_b   = (const float*)d_in[12];
    float* out = (float*)d_out;

    float *xproj, *sseq, *rx, *ux, *nx, *u, *logits, *att, *rbuf, *uebuf, *hb, *hp, *zero;
    cudaGetSymbolAddress((void**)&xproj, g_xproj);
    cudaGetSymbolAddress((void**)&sseq,  g_sseq);
    cudaGetSymbolAddress((void**)&rx,    g_rx);
    cudaGetSymbolAddress((void**)&ux,    g_ux);
    cudaGetSymbolAddress((void**)&nx,    g_nx);
    cudaGetSymbolAddress((void**)&u,     g_u);
    cudaGetSymbolAddress((void**)&logits,g_logits);
    cudaGetSymbolAddress((void**)&att,   g_att);
    cudaGetSymbolAddress((void**)&rbuf,  g_r);
    cudaGetSymbolAddress((void**)&uebuf, g_ue);
    cudaGetSymbolAddress((void**)&hb,    g_h);
    cudaGetSymbolAddress((void**)&hp,    g_hp);
    cudaGetSymbolAddress((void**)&zero,  g_zero);

    zero_kernel<<<(BB * DD + 255) / 256, 256>>>(zero, BB * DD);

    // 1) x_proj[B,L,3D] = session @ Wih^T + bih   (rows = b*L+l, no remap)
    {
        dim3 g(BB * LL / 64, 3 * DD / 64);
        mm_big<<<g, 128>>>(session, DD, wih, DD, 0, bih, xproj, 3 * DD);
    }

    // 2) GRU recurrence; s_seq [L,B,D] holds h history (h0 = 0)
    {
        dim3 gm(BB / 64, 3 * DD / 64);
        for (int l = 0; l < LL; l++) {
            const float* hprev = (l == 0) ? zero : sseq + (size_t)(l - 1) * BB * DD;
            mm_big<<<gm, 128>>>(hprev, DD, whh, DD, 0, bhh, hp, 3 * DD);
            gru_gate<<<BB * DD / 256, 256>>>(hp, xproj, l, hprev,
                                             sseq + (size_t)l * BB * DD);
        }
    }

    // 3) u[b,:] = w @ target[b]
    {
        dim3 g(BB / 64, DD / 64);
        mm_big<<<g, 128>>>(target, DD, w, DD, 0, nullptr, u, DD);
    }

    // 4) AUGRU x-projections (x = s_seq rows l*B+b), biases folded
    {
        dim3 g(BB * LL / 64, DD / 64);
        mm_big<<<g, 128>>>(sseq, DD, reset_w,  2 * DD, DD, reset_b,  rx, DD);
        mm_big<<<g, 128>>>(sseq, DD, update_w, 2 * DD, DD, update_b, ux, DD);
        mm_big<<<g, 128>>>(sseq, DD, hhat_w,   2 * DD, DD, hhat_b,   nx, DD);
    }

    // 5) attention
    attn_logits<<<LL * BB / 8, 256>>>(sseq, u, logits);
    attn_softmax<<<BB, 256>>>(logits, att);

    // 6) AUGRU recurrence; init h = s_seq[L-1]; last step writes d_out
    {
        dim3 ga(BB / 64, DD / 64, 2);
        dim3 gb(BB / 64, DD / 64);
        for (int l = 0; l < LL; l++) {
            const float* hc = (l == 0) ? sseq + (size_t)(LL - 1) * BB * DD
                                       : hb + (size_t)(l & 1) * BB * DD;
            float* ho = (l == LL - 1) ? out : hb + (size_t)((l + 1) & 1) * BB * DD;
            mm_aua<<<ga, 128>>>(hc, reset_w, update_w,
                                rx + (size_t)l * BB * DD,
                                ux + (size_t)l * BB * DD,
                                att + l * BB, rbuf, uebuf);
            mm_aub<<<gb, 128>>>(hc, rbuf, hhat_w,
                                nx + (size_t)l * BB * DD, uebuf, ho);
        }
    }
}